// round 5
// baseline (speedup 1.0000x reference)
#include <cuda_runtime.h>

// Fused 1-level DWT (analysis lowpass, stride 2, symmetric pad) + synthesis
// lowpass (transposed conv, dilation 2). 64 rows of length 524288.
//
//   cA[m]    = sum_i H[i] * sig_mir(2m + i - 8)
//   ya[2u]   = sum_r H[8-2r] * cA[u+r]
//   ya[2u+1] = sum_r H[9-2r] * cA[u+r]
// mirror: q<0 -> -1-q ; q>=L -> 2L-1-q.
//
// R5: one float4 of output per thread, lane-contiguous. The 20-float input
// window is 5 overlapping float4 loads gf-2..gf+2 — each one a DENSE coalesced
// LDG.128 (4 lines/warp; overlap across the 5 loads hits in L1). Dense STG.
// No smem, no barrier, no shuffles. L1 wavefronts: 24 per 128 outputs vs 67
// per 256 in the best prior kernel.

#define THREADS 256

__global__ __launch_bounds__(THREADS)
void wavelet_dense_kernel(const float* __restrict__ x,
                          float* __restrict__ y,
                          int Lf4, int blocksPerRow)
{
    const int blk = blockIdx.x;
    const int row = blockIdx.y;
    const long long rowbase = (long long)row * (long long)Lf4 * 4LL;
    const float* xr = x + rowbase;

    const int gf = blk * THREADS + threadIdx.x;   // output float4 index in row

    float xv[20];  // sig[4gf-8 .. 4gf+11]

    if (blk == 0 || blk == blocksPerRow - 1) {
        // boundary blocks (128 of 32768): scalar mirrored loads
        const int L = Lf4 * 4;
        const int t0 = gf * 4;
        #pragma unroll
        for (int i = 0; i < 20; i++) {
            int q = t0 - 8 + i;
            if (q < 0)        q = -1 - q;
            else if (q >= L)  q = 2 * L - 1 - q;
            xv[i] = xr[q];
        }
    } else {
        // interior: 5 dense coalesced LDG.128 (independent -> high MLP)
        const float4* xf4 = reinterpret_cast<const float4*>(xr) + gf;
        float4 m2 = xf4[-2];
        float4 m1 = xf4[-1];
        float4 c0 = xf4[ 0];
        float4 p1 = xf4[ 1];
        float4 p2 = xf4[ 2];
        xv[0]=m2.x;  xv[1]=m2.y;  xv[2]=m2.z;  xv[3]=m2.w;
        xv[4]=m1.x;  xv[5]=m1.y;  xv[6]=m1.z;  xv[7]=m1.w;
        xv[8]=c0.x;  xv[9]=c0.y;  xv[10]=c0.z; xv[11]=c0.w;
        xv[12]=p1.x; xv[13]=p1.y; xv[14]=p1.z; xv[15]=p1.w;
        xv[16]=p2.x; xv[17]=p2.y; xv[18]=p2.z; xv[19]=p2.w;
    }

    constexpr float H[10] = {
        0.160102397974125f,     0.6038292697974729f,
        0.7243085284385744f,    0.13842814590110342f,
       -0.24229488706619015f,  -0.03224486958502952f,
        0.07757149384006515f,  -0.006241490213011705f,
       -0.012580751999015526f,  0.003335725285001549f
    };

    // stage 1: 6 approximation coefficients cA[2gf + r], r = 0..5
    float cA[6];
    #pragma unroll
    for (int r = 0; r < 6; r++) {
        float a = 0.0f;
        #pragma unroll
        for (int i = 0; i < 10; i++) {
            a = fmaf(H[i], xv[2*r + i], a);
        }
        cA[r] = a;
    }

    // stage 2: 4 outputs (2 even/odd pairs)
    float o[4];
    #pragma unroll
    for (int s = 0; s < 2; s++) {
        float e = 0.0f, od = 0.0f;
        #pragma unroll
        for (int rp = 0; rp < 5; rp++) {
            e  = fmaf(H[8 - 2*rp], cA[s + rp], e);
            od = fmaf(H[9 - 2*rp], cA[s + rp], od);
        }
        o[2*s + 0] = e;
        o[2*s + 1] = od;
    }

    // dense coalesced store
    reinterpret_cast<float4*>(y + rowbase)[gf] = make_float4(o[0], o[1], o[2], o[3]);
}

extern "C" void kernel_launch(void* const* d_in, const int* in_sizes, int n_in,
                              void* d_out, int out_size)
{
    const float* x = (const float*)d_in[0];
    float* y = (float*)d_out;

    const int B = 64;
    const int total = in_sizes[0];            // 64 * 128 * 4096
    const int L = total / B;                  // 524288
    const int Lf4 = L / 4;                    // 131072
    const int blocksPerRow = Lf4 / THREADS;   // 512

    dim3 grid(blocksPerRow, B);
    wavelet_dense_kernel<<<grid, THREADS>>>(x, y, Lf4, blocksPerRow);
}

// round 6
// speedup vs baseline: 1.0114x; 1.0114x over previous
#include <cuda_runtime.h>

// Fused 1-level DWT (analysis lowpass, stride 2, symmetric pad) + synthesis
// lowpass (transposed conv, dilation 2). 64 rows of length 524288.
//
//   cA[m]    = sum_i H[i] * sig_mir(2m + i - 8)
//   ya[2u]   = sum_r H[8-2r] * cA[u+r]
//   ya[2u+1] = sum_r H[9-2r] * cA[u+r]
// mirror: q<0 -> -1-q ; q>=L -> 2L-1-q.
//
// R6: two lane-contiguous segments per thread (output float4s gA and gA+256).
// All 10 loads + 2 stores are dense coalesced 128-bit accesses; 10 independent
// front-batched loads give MLP~10/thread. 8 outputs/thread restores R2's
// instruction efficiency while keeping R5's minimal L1 wavefront count.

#define THREADS 256
#define TILE4   512    // output float4s per block (2048 floats)

__device__ __forceinline__ void seg_compute(const float xv[20], float o[4])
{
    constexpr float H[10] = {
        0.160102397974125f,     0.6038292697974729f,
        0.7243085284385744f,    0.13842814590110342f,
       -0.24229488706619015f,  -0.03224486958502952f,
        0.07757149384006515f,  -0.006241490213011705f,
       -0.012580751999015526f,  0.003335725285001549f
    };

    float cA[6];
    #pragma unroll
    for (int r = 0; r < 6; r++) {
        float a = 0.0f;
        #pragma unroll
        for (int i = 0; i < 10; i++) {
            a = fmaf(H[i], xv[2*r + i], a);
        }
        cA[r] = a;
    }

    #pragma unroll
    for (int s = 0; s < 2; s++) {
        float e = 0.0f, od = 0.0f;
        #pragma unroll
        for (int rp = 0; rp < 5; rp++) {
            e  = fmaf(H[8 - 2*rp], cA[s + rp], e);
            od = fmaf(H[9 - 2*rp], cA[s + rp], od);
        }
        o[2*s + 0] = e;
        o[2*s + 1] = od;
    }
}

__device__ __forceinline__ void unpack5(const float4 v[5], float xv[20])
{
    #pragma unroll
    for (int k = 0; k < 5; k++) {
        xv[4*k+0] = v[k].x; xv[4*k+1] = v[k].y;
        xv[4*k+2] = v[k].z; xv[4*k+3] = v[k].w;
    }
}

__global__ __launch_bounds__(THREADS)
void wavelet_2seg_kernel(const float* __restrict__ x,
                         float* __restrict__ y,
                         int Lf4, int blocksPerRow)
{
    const int blk = blockIdx.x;
    const int row = blockIdx.y;
    const long long rowbase = (long long)row * (long long)Lf4 * 4LL;
    const float* xr = x + rowbase;

    const int gA = blk * TILE4 + threadIdx.x;       // segment A float4 index
    const int gB = gA + THREADS;                     // segment B float4 index

    float xvA[20], xvB[20];

    if (blk == 0 || blk == blocksPerRow - 1) {
        // boundary blocks (128 of 16384): scalar mirrored loads
        const int L = Lf4 * 4;
        #pragma unroll
        for (int i = 0; i < 20; i++) {
            int qa = gA * 4 - 8 + i;
            if (qa < 0)        qa = -1 - qa;
            else if (qa >= L)  qa = 2 * L - 1 - qa;
            xvA[i] = xr[qa];
            int qb = gB * 4 - 8 + i;
            if (qb < 0)        qb = -1 - qb;
            else if (qb >= L)  qb = 2 * L - 1 - qb;
            xvB[i] = xr[qb];
        }
    } else {
        // interior: 10 dense coalesced LDG.128, all independent (front-batched)
        const float4* a4 = reinterpret_cast<const float4*>(xr) + gA;
        const float4* b4 = reinterpret_cast<const float4*>(xr) + gB;
        float4 va[5], vb[5];
        #pragma unroll
        for (int k = 0; k < 5; k++) va[k] = a4[k - 2];
        #pragma unroll
        for (int k = 0; k < 5; k++) vb[k] = b4[k - 2];
        unpack5(va, xvA);
        unpack5(vb, xvB);
    }

    float oA[4], oB[4];
    seg_compute(xvA, oA);
    seg_compute(xvB, oB);

    float4* yo = reinterpret_cast<float4*>(y + rowbase);
    yo[gA] = make_float4(oA[0], oA[1], oA[2], oA[3]);
    yo[gB] = make_float4(oB[0], oB[1], oB[2], oB[3]);
}

extern "C" void kernel_launch(void* const* d_in, const int* in_sizes, int n_in,
                              void* d_out, int out_size)
{
    const float* x = (const float*)d_in[0];
    float* y = (float*)d_out;

    const int B = 64;
    const int total = in_sizes[0];            // 64 * 128 * 4096
    const int L = total / B;                  // 524288
    const int Lf4 = L / 4;                    // 131072
    const int blocksPerRow = Lf4 / TILE4;     // 256

    dim3 grid(blocksPerRow, B);
    wavelet_2seg_kernel<<<grid, THREADS>>>(x, y, Lf4, blocksPerRow);
}

// round 8
// speedup vs baseline: 1.0537x; 1.0418x over previous
#include <cuda_runtime.h>

// Fused 1-level DWT (analysis lowpass, stride 2, symmetric pad) + synthesis
// lowpass (transposed conv, dilation 2). 64 rows of length 524288.
//
//   cA[m]    = sum_i H[i] * sig_mir(2m + i - 8)
//   ya[2u]   = sum_r H[8-2r] * cA[u+r]
//   ya[2u+1] = sum_r H[9-2r] * cA[u+r]
// mirror: q<0 -> -1-q ; q>=L -> 2L-1-q.
//
// R7: dense lane-contiguous float4 mapping (minimal L1 wavefronts) + software
// pipelining: each block walks 8 chunks of 256 float4s, prefetching the next
// chunk's 5 dense LDG.128 before computing the current one. Latency is hidden
// by cross-iteration ILP instead of occupancy.

#define THREADS 256
#define ITERS   8
#define CHUNK   THREADS                  // float4s per iteration
#define BLK4    (ITERS * CHUNK)          // float4s per block (2048)

struct Win { float4 v[5]; };

__device__ __forceinline__ void load_dense(const float4* __restrict__ xf4,
                                           int g, Win& w)
{
    #pragma unroll
    for (int k = 0; k < 5; k++) w.v[k] = xf4[g + k - 2];
}

__device__ __forceinline__ void load_mirror(const float* __restrict__ xr,
                                            int g, int L, Win& w)
{
    #pragma unroll
    for (int k = 0; k < 5; k++) {
        float t[4];
        #pragma unroll
        for (int c = 0; c < 4; c++) {
            int q = (g + k - 2) * 4 + c;
            if (q < 0)        q = -1 - q;
            else if (q >= L)  q = 2 * L - 1 - q;
            t[c] = xr[q];
        }
        w.v[k] = make_float4(t[0], t[1], t[2], t[3]);
    }
}

__device__ __forceinline__ float4 win_compute(const Win& w)
{
    constexpr float H[10] = {
        0.160102397974125f,     0.6038292697974729f,
        0.7243085284385744f,    0.13842814590110342f,
       -0.24229488706619015f,  -0.03224486958502952f,
        0.07757149384006515f,  -0.006241490213011705f,
       -0.012580751999015526f,  0.003335725285001549f
    };

    float xv[20];
    #pragma unroll
    for (int k = 0; k < 5; k++) {
        xv[4*k+0] = w.v[k].x; xv[4*k+1] = w.v[k].y;
        xv[4*k+2] = w.v[k].z; xv[4*k+3] = w.v[k].w;
    }

    float cA[6];
    #pragma unroll
    for (int r = 0; r < 6; r++) {
        float a = 0.0f;
        #pragma unroll
        for (int i = 0; i < 10; i++) {
            a = fmaf(H[i], xv[2*r + i], a);
        }
        cA[r] = a;
    }

    float o[4];
    #pragma unroll
    for (int s = 0; s < 2; s++) {
        float e = 0.0f, od = 0.0f;
        #pragma unroll
        for (int rp = 0; rp < 5; rp++) {
            e  = fmaf(H[8 - 2*rp], cA[s + rp], e);
            od = fmaf(H[9 - 2*rp], cA[s + rp], od);
        }
        o[2*s + 0] = e;
        o[2*s + 1] = od;
    }
    return make_float4(o[0], o[1], o[2], o[3]);
}

__global__ __launch_bounds__(THREADS)
void wavelet_pipe_kernel(const float* __restrict__ x,
                         float* __restrict__ y,
                         int Lf4, int blocksPerRow)
{
    const int blk = blockIdx.x;
    const int row = blockIdx.y;
    const long long rowbase = (long long)row * (long long)Lf4 * 4LL;
    const float* xr = x + rowbase;
    const float4* xf4 = reinterpret_cast<const float4*>(xr);
    float4* yo = reinterpret_cast<float4*>(y + rowbase);

    const int L = Lf4 * 4;
    const int g0 = blk * BLK4 + threadIdx.x;   // iteration-0 float4 index
    const bool leftEdge  = (blk == 0);
    const bool rightEdge = (blk == blocksPerRow - 1);

    Win cur;
    if (leftEdge) load_mirror(xr, g0, L, cur);
    else          load_dense(xf4, g0, cur);

    #pragma unroll 2
    for (int it = 0; it < ITERS; it++) {
        const int g = g0 + it * CHUNK;

        Win nxt;
        if (it + 1 < ITERS) {
            if (rightEdge && (it + 1 == ITERS - 1))
                load_mirror(xr, g + CHUNK, L, nxt);
            else
                load_dense(xf4, g + CHUNK, nxt);
        }

        yo[g] = win_compute(cur);

        cur = nxt;
    }
}

extern "C" void kernel_launch(void* const* d_in, const int* in_sizes, int n_in,
                              void* d_out, int out_size)
{
    const float* x = (const float*)d_in[0];
    float* y = (float*)d_out;

    const int B = 64;
    const int total = in_sizes[0];            // 64 * 128 * 4096
    const int L = total / B;                  // 524288
    const int Lf4 = L / 4;                    // 131072
    const int blocksPerRow = Lf4 / BLK4;      // 64

    dim3 grid(blocksPerRow, B);
    wavelet_pipe_kernel<<<grid, THREADS>>>(x, y, Lf4, blocksPerRow);
}

// round 9
// speedup vs baseline: 1.2348x; 1.1719x over previous
#include <cuda_runtime.h>

// Fused 1-level DWT (analysis lowpass, stride 2, symmetric pad) + synthesis
// lowpass (transposed conv, dilation 2). 64 rows of length 524288.
//
//   cA[m]    = sum_i H[i] * sig_mir(2m + i - 8)
//   ya[2u]   = sum_r H[8-2r] * cA[u+r]
//   ya[2u+1] = sum_r H[9-2r] * cA[u+r]
// mirror: q<0 -> -1-q ; q>=L -> 2L-1-q.
//
// R8: R2 mapping (8 outputs/thread, t0 = tile*2048 + tid*8) but with Blackwell
// 256-bit global accesses (ld/st.global.v8.f32). At 32B/lane, lane-stride
// 32B, each v8 access is a fully dense 1024B warp transaction (8 L1
// wavefronts, 100% line efficiency) vs the 50%-efficient strided LDG.128
// pairs. L1 work: 32 wf/256 outputs vs 67 in the prior best.

#define TILE      2048
#define THREADS   256
#define PER_THR   8

__device__ __forceinline__ void ldg256(const float* __restrict__ p, float v[8])
{
    asm volatile("ld.global.nc.v8.f32 {%0,%1,%2,%3,%4,%5,%6,%7}, [%8];"
                 : "=f"(v[0]), "=f"(v[1]), "=f"(v[2]), "=f"(v[3]),
                   "=f"(v[4]), "=f"(v[5]), "=f"(v[6]), "=f"(v[7])
                 : "l"(p));
}

__device__ __forceinline__ void stg256(float* p, const float v[8])
{
    asm volatile("st.global.v8.f32 [%0], {%1,%2,%3,%4,%5,%6,%7,%8};"
                 :: "l"(p),
                    "f"(v[0]), "f"(v[1]), "f"(v[2]), "f"(v[3]),
                    "f"(v[4]), "f"(v[5]), "f"(v[6]), "f"(v[7])
                 : "memory");
}

__global__ __launch_bounds__(THREADS)
void wavelet_v8_kernel(const float* __restrict__ x,
                       float* __restrict__ y,
                       int L, int tilesPerRow)
{
    const int tile = blockIdx.x;
    const int row  = blockIdx.y;
    const long long rowbase = (long long)row * (long long)L;
    const float* xr = x + rowbase;

    const int t0 = tile * TILE + threadIdx.x * PER_THR;  // first output index

    float xv[24];  // sig[t0-8 .. t0+15]

    if (tile == 0 || tile == tilesPerRow - 1) {
        // boundary tiles (128 of 16384 blocks): scalar mirrored loads
        #pragma unroll
        for (int i = 0; i < 24; i++) {
            int q = t0 - 8 + i;
            if (q < 0)        q = -1 - q;
            else if (q >= L)  q = 2 * L - 1 - q;
            xv[i] = xr[q];
        }
    } else {
        // interior: 3 independent dense 256-bit loads (32B-aligned)
        ldg256(xr + t0 - 8, xv + 0);
        ldg256(xr + t0,     xv + 8);
        ldg256(xr + t0 + 8, xv + 16);
    }

    constexpr float H[10] = {
        0.160102397974125f,     0.6038292697974729f,
        0.7243085284385744f,    0.13842814590110342f,
       -0.24229488706619015f,  -0.03224486958502952f,
        0.07757149384006515f,  -0.006241490213011705f,
       -0.012580751999015526f,  0.003335725285001549f
    };

    // stage 1: 8 approximation coefficients
    float cA[8];
    #pragma unroll
    for (int r = 0; r < 8; r++) {
        float a = 0.0f;
        #pragma unroll
        for (int i = 0; i < 10; i++) {
            a = fmaf(H[i], xv[2*r + i], a);
        }
        cA[r] = a;
    }

    // stage 2: 8 outputs (4 even/odd pairs)
    float o[8];
    #pragma unroll
    for (int s = 0; s < 4; s++) {
        float e = 0.0f, od = 0.0f;
        #pragma unroll
        for (int rp = 0; rp < 5; rp++) {
            e  = fmaf(H[8 - 2*rp], cA[s + rp], e);
            od = fmaf(H[9 - 2*rp], cA[s + rp], od);
        }
        o[2*s + 0] = e;
        o[2*s + 1] = od;
    }

    // one dense 256-bit store (32B-aligned)
    stg256(y + rowbase + t0, o);
}

extern "C" void kernel_launch(void* const* d_in, const int* in_sizes, int n_in,
                              void* d_out, int out_size)
{
    const float* x = (const float*)d_in[0];
    float* y = (float*)d_out;

    const int B = 64;
    const int total = in_sizes[0];          // 64 * 128 * 4096
    const int L = total / B;                // 524288
    const int tilesPerRow = L / TILE;       // 256

    dim3 grid(tilesPerRow, B);
    wavelet_v8_kernel<<<grid, THREADS>>>(x, y, L, tilesPerRow);
}